// round 2
// baseline (speedup 1.0000x reference)
#include <cuda_runtime.h>
#include <cstdint>

// Problem: out[b,l,h] = data[b,l,h] * mask(b,l)
//   mask = l < a_end        -> 1 - (a_end - l)/C
//          elif l < s_len   -> 1 - (l - a_idx)/C
//          else             -> 0
// B=512, L=512, H=100, C=40. Pure HBM-bound elementwise op.
// NOTE: index arrays are int32 on disk (JAX default x32 downcasts the
// requested int64), so we read them as const int*.

#define B_DIM 512
#define L_DIM 512
#define H_DIM 100
#define VEC_PER_ROW (H_DIM / 4)          // 25 float4 per (b,l) row
#define TOTAL_VEC (B_DIM * L_DIM * VEC_PER_ROW)
#define C_INV (1.0f / 40.0f)

__global__ __launch_bounds__(256) void mask_mul_kernel(
    const float4* __restrict__ data,
    const int* __restrict__ aspect_index,
    const int* __restrict__ aspect_len,
    const int* __restrict__ sents_len,
    float4* __restrict__ out)
{
    int t = blockIdx.x * blockDim.x + threadIdx.x;
    if (t >= TOTAL_VEC) return;

    // t -> (b, l, v); divisions by compile-time constants become mul-shift.
    int row = t / VEC_PER_ROW;           // b * L + l
    int b = row / L_DIM;
    int l = row - b * L_DIM;

    // Per-batch scalars: broadcast loads, L1/L2 resident.
    int a_idx = aspect_index[b];
    int a_end = a_idx + aspect_len[b];
    int s_len = sents_len[b];

    float i_f = (float)l;
    float mask;
    if (l < a_end) {
        mask = 1.0f - ((float)a_end - i_f) * C_INV;
    } else if (l < s_len) {
        mask = 1.0f - (i_f - (float)a_idx) * C_INV;
    } else {
        mask = 0.0f;
    }

    float4 v = data[t];
    v.x *= mask; v.y *= mask; v.z *= mask; v.w *= mask;
    out[t] = v;
}

extern "C" void kernel_launch(void* const* d_in, const int* in_sizes, int n_in,
                              void* d_out, int out_size)
{
    const float4* data = (const float4*)d_in[0];
    const int*    aidx = (const int*)d_in[1];
    const int*    alen = (const int*)d_in[2];
    const int*    slen = (const int*)d_in[3];
    float4* out = (float4*)d_out;

    const int threads = 256;
    const int blocks = (TOTAL_VEC + threads - 1) / threads;
    mask_mul_kernel<<<blocks, threads>>>(data, aidx, alen, slen, out);
}

// round 3
// speedup vs baseline: 1.0887x; 1.0887x over previous
#include <cuda_runtime.h>
#include <cstdint>

// out[b,l,h] = data[b,l,h] * mask(b,l)
//   mask = l < a_end      -> 1 - (a_end - l)/C
//          elif l < s_len -> 1 - (l - a_idx)/C
//          else           -> 0
// B=512, L=512, H=100, C=40. HBM-bound streaming multiply.
// Index arrays are int32 (JAX x32 downcasts the requested int64).
//
// K=4 float4 per thread, loads batched up front -> MLP_p1=4 for latency
// hiding; scalar index loads amortized 4x.

#define B_DIM 512
#define L_DIM 512
#define H_DIM 100
#define VEC_PER_ROW (H_DIM / 4)                      // 25
#define TOTAL_VEC (B_DIM * L_DIM * VEC_PER_ROW)      // 6,553,600
#define KPT 4
#define THREADS 256
#define BLOCKS (TOTAL_VEC / (THREADS * KPT))         // 6400, exact

#define C_INV (1.0f / 40.0f)

__device__ __forceinline__ float row_mask(int l, int a_idx, int a_end, int s_len)
{
    float i_f = (float)l;
    if (l < a_end)  return 1.0f - ((float)a_end - i_f) * C_INV;
    if (l < s_len)  return 1.0f - (i_f - (float)a_idx) * C_INV;
    return 0.0f;
}

__global__ __launch_bounds__(THREADS) void mask_mul_kernel(
    const float4* __restrict__ data,
    const int* __restrict__ aspect_index,
    const int* __restrict__ aspect_len,
    const int* __restrict__ sents_len,
    float4* __restrict__ out)
{
    int base = blockIdx.x * (THREADS * KPT) + threadIdx.x;

    // Batch the 4 stream loads up front (independent -> MLP_p1 = 4).
    float4 v[KPT];
    int idx[KPT];
#pragma unroll
    for (int k = 0; k < KPT; k++) {
        idx[k] = base + k * THREADS;
        v[k] = data[idx[k]];
    }

#pragma unroll
    for (int k = 0; k < KPT; k++) {
        int row = idx[k] / VEC_PER_ROW;      // b*L + l  (const div -> mulhi)
        int b = row >> 9;                    // / L_DIM
        int l = row & (L_DIM - 1);

        int a_idx = __ldg(&aspect_index[b]);
        int a_end = a_idx + __ldg(&aspect_len[b]);
        int s_len = __ldg(&sents_len[b]);

        float m = row_mask(l, a_idx, a_end, s_len);
        v[k].x *= m; v[k].y *= m; v[k].z *= m; v[k].w *= m;
        out[idx[k]] = v[k];
    }
}

extern "C" void kernel_launch(void* const* d_in, const int* in_sizes, int n_in,
                              void* d_out, int out_size)
{
    const float4* data = (const float4*)d_in[0];
    const int*    aidx = (const int*)d_in[1];
    const int*    alen = (const int*)d_in[2];
    const int*    slen = (const int*)d_in[3];
    float4* out = (float4*)d_out;

    mask_mul_kernel<<<BLOCKS, THREADS>>>(data, aidx, alen, slen, out);
}

// round 4
// speedup vs baseline: 1.1111x; 1.0206x over previous
#include <cuda_runtime.h>
#include <cstdint>

// out[b,l,h] = data[b,l,h] * mask(b,l)
//   mask = l < a_end      -> 1 - (a_end - l)/C
//          elif l < s_len -> 1 - (l - a_idx)/C
//          else           -> 0
// B=512, L=512, H=100, C=40. HBM-bound streaming multiply.
// Index arrays are int32 (JAX x32 downcasts the requested int64).
//
// KPT=8 float4 per thread, all loads batched up front (MLP_p1=8) with
// streaming cache hints (__ldcs/__stcs): working set 210MB > L2 126MB,
// so evict-first avoids pointless L2 thrash.

#define B_DIM 512
#define L_DIM 512
#define H_DIM 100
#define VEC_PER_ROW (H_DIM / 4)                      // 25
#define TOTAL_VEC (B_DIM * L_DIM * VEC_PER_ROW)      // 6,553,600
#define KPT 8
#define THREADS 256
#define BLOCKS (TOTAL_VEC / (THREADS * KPT))         // 3200, exact

#define C_INV (1.0f / 40.0f)

__device__ __forceinline__ float row_mask(int l, int a_idx, int a_end, int s_len)
{
    float i_f = (float)l;
    if (l < a_end)  return 1.0f - ((float)a_end - i_f) * C_INV;
    if (l < s_len)  return 1.0f - (i_f - (float)a_idx) * C_INV;
    return 0.0f;
}

__global__ __launch_bounds__(THREADS) void mask_mul_kernel(
    const float4* __restrict__ data,
    const int* __restrict__ aspect_index,
    const int* __restrict__ aspect_len,
    const int* __restrict__ sents_len,
    float4* __restrict__ out)
{
    int base = blockIdx.x * (THREADS * KPT) + threadIdx.x;

    // Front-batch all 8 stream loads (independent -> MLP_p1 = 8).
    float4 v[KPT];
#pragma unroll
    for (int k = 0; k < KPT; k++) {
        v[k] = __ldcs(&data[base + k * THREADS]);
    }

#pragma unroll
    for (int k = 0; k < KPT; k++) {
        int idx = base + k * THREADS;
        int row = idx / VEC_PER_ROW;         // b*L + l  (const div -> mulhi)
        int b = row >> 9;                    // / L_DIM
        int l = row & (L_DIM - 1);

        int a_idx = __ldg(&aspect_index[b]);
        int a_end = a_idx + __ldg(&aspect_len[b]);
        int s_len = __ldg(&sents_len[b]);

        float m = row_mask(l, a_idx, a_end, s_len);
        v[k].x *= m; v[k].y *= m; v[k].z *= m; v[k].w *= m;
        __stcs(&out[idx], v[k]);
    }
}

extern "C" void kernel_launch(void* const* d_in, const int* in_sizes, int n_in,
                              void* d_out, int out_size)
{
    const float4* data = (const float4*)d_in[0];
    const int*    aidx = (const int*)d_in[1];
    const int*    alen = (const int*)d_in[2];
    const int*    slen = (const int*)d_in[3];
    float4* out = (float4*)d_out;

    mask_mul_kernel<<<BLOCKS, THREADS>>>(data, aidx, alen, slen, out);
}